// round 1
// baseline (speedup 1.0000x reference)
#include <cuda_runtime.h>

// NSE_layer: fused Navier-Stokes residual + BC-mask outputs on a 2048x2048 grid.
// Outputs (flat concat): loss_nse (3,3,2046,2046) | G_bc_mask (1,3,2048,2048) | G_bc_v (2,1,3,2048,2048)

#define GNX 2048
#define GNY 2048
#define TSX 32
#define TSY 8

__device__ unsigned char g_row_in[GNY];
__device__ unsigned char g_row_out[GNY];

__global__ void row_flags_kernel(const int* __restrict__ lay) {
    int y = blockIdx.x;
    const int* row = lay + (size_t)y * GNX;
    int fin = 0, fout = 0;
    for (int x = threadIdx.x; x < GNX; x += blockDim.x) {
        int L = __ldg(row + x);
        fin  |= (L == 1);
        fout |= (L == 3);
    }
    fin  = __syncthreads_or(fin);
    fout = __syncthreads_or(fout);
    if (threadIdx.x == 0) {
        g_row_in[y]  = (unsigned char)(fin  ? 1 : 0);
        g_row_out[y] = (unsigned char)(fout ? 1 : 0);
    }
}

__global__ __launch_bounds__(TSX * TSY)
void nse_main_kernel(const int* __restrict__ lay,
                     const float* __restrict__ f0,
                     const float* __restrict__ f1,
                     const float* __restrict__ f2,
                     float* __restrict__ out_loss,
                     float* __restrict__ out_mask,
                     float* __restrict__ out_gbv)
{
    __shared__ float su[TSY + 2][TSX + 4];
    __shared__ float sv[TSY + 2][TSX + 4];
    __shared__ float sp[TSY + 2][TSX + 4];

    const int bx = blockIdx.x * TSX;
    const int by = blockIdx.y * TSY;
    const int tid = threadIdx.y * TSX + threadIdx.x;
    const size_t NP = (size_t)GNX * GNY;

    // Cooperative tile fill: materialize u, v, p (flow with BC masks applied)
    for (int t = tid; t < (TSY + 2) * (TSX + 2); t += TSX * TSY) {
        int ly = t / (TSX + 2);
        int lx = t - ly * (TSX + 2);
        int Y = by + ly - 1;
        int X = bx + lx - 1;
        float u = 0.f, v = 0.f, p = 0.f;
        if (Y >= 0 && Y < GNY && X >= 0 && X < GNX) {
            size_t idx = (size_t)Y * GNX + X;
            int L = __ldg(lay + idx);
            float base = (L == 2) ? 0.f : 1.f;
            float gb0 = base, gb1 = base, gb2 = base, gv0 = 0.f;
            if (X == 0 && g_row_in[Y])        { gb0 = 0.f; gb1 = 0.f; gv0 = 3.f; }
            if (X == GNX - 1 && g_row_out[Y]) { gb2 = 0.f; }
            u = __ldg(f0 + idx) * gb0 + gv0;
            v = __ldg(f1 + idx) * gb1;
            p = __ldg(f2 + idx) * gb2;
        }
        su[ly][lx] = u;
        sv[ly][lx] = v;
        sp[ly][lx] = p;
    }
    __syncthreads();

    const int X = bx + threadIdx.x;
    const int Y = by + threadIdx.y;
    const size_t idx = (size_t)Y * GNX + X;
    const int L = __ldg(lay + idx);

    // ---- boundary/mask outputs (full 2048x2048) ----
    {
        float base = (L == 2) ? 0.f : 1.f;
        float gb0 = base, gb1 = base, gb2 = base, gv0 = 0.f;
        if (X == 0 && g_row_in[Y])        { gb0 = 0.f; gb1 = 0.f; gv0 = 3.f; }
        if (X == GNX - 1 && g_row_out[Y]) { gb2 = 0.f; }
        float keep = (L > 3) ? 0.f : 1.f;
        float code = (L > 3) ? (float)L : 0.f;

        out_mask[0 * NP + idx] = gb0 * keep + code;
        out_mask[1 * NP + idx] = gb1 * keep + code;
        out_mask[2 * NP + idx] = gb2 * keep + code;

        out_gbv[0 * NP + idx] = gb0;   // G_bc ch0
        out_gbv[1 * NP + idx] = gb1;   // G_bc ch1
        out_gbv[2 * NP + idx] = gb2;   // G_bc ch2
        out_gbv[3 * NP + idx] = gv0;   // G_bc_value ch0 (3.0 at inlet col 0)
        out_gbv[4 * NP + idx] = 0.f;   // G_bc_value ch1
        out_gbv[5 * NP + idx] = 0.f;   // G_bc_value ch2
    }

    // ---- NSE residual (interior 2046x2046) ----
    if (X >= 1 && X < GNX - 1 && Y >= 1 && Y < GNY - 1) {
        const int i = threadIdx.y + 1;
        const int j = threadIdx.x + 1;
        const float h      = (float)(0.1 / 2047.0);
        const float inv_h  = 1.0f / h;
        const float nu_h2  = 0.05f / (h * h);

        float uc = su[i][j], ul = su[i][j-1], ur = su[i][j+1], un = su[i-1][j], us = su[i+1][j];
        float vc = sv[i][j], vl = sv[i][j-1], vr = sv[i][j+1], vn = sv[i-1][j], vs = sv[i+1][j];
        float pc = sp[i][j], pl = sp[i][j-1], pr = sp[i][j+1], pn = sp[i-1][j], ps = sp[i+1][j];

        float dxu = 0.5f * (ur - ul);
        float dyu = 0.5f * (us - un);
        float dxv = 0.5f * (vr - vl);
        float dyv = 0.5f * (vs - vn);
        float lapu = un + us + ul + ur - 4.0f * uc;
        float lapv = vn + vs + vl + vr - 4.0f * vc;
        float cont = dxu * inv_h + dyv * inv_h;

        // pressure-gradient flavor per layout case
        bool fx  = (L == 4) | (L == 8)  | (L == 11);
        bool bxd = (L == 6) | (L == 9)  | (L == 10);
        bool fy  = (L == 7) | (L == 10) | (L == 11);
        bool byd = (L == 5) | (L == 8)  | (L == 9);
        float dpx = fx  ? (pr - pc) : (bxd ? (pc - pl) : 0.5f * (pr - pl));
        float dpy = fy  ? (pn - pc) : (byd ? (pc - ps) : 0.5f * (ps - pn));

        float mu = uc * dxu * inv_h + vc * dyu * inv_h + dpx * inv_h - lapu * nu_h2;
        float mv = uc * dxv * inv_h + vc * dyv * inv_h + dpy * inv_h - lapv * nu_h2;

        float m = (L == 2) ? 0.f : 1.f;
        float r0 = m * mu, r1 = m * mv, r2 = m * cont;

        const size_t NN = (size_t)(GNX - 2) * (GNY - 2);
        size_t li = (size_t)(Y - 1) * (GNX - 2) + (X - 1);
        #pragma unroll
        for (int jj = 0; jj < 3; jj++) {
            out_loss[(0 * 3 + jj) * NN + li] = r0;
            out_loss[(1 * 3 + jj) * NN + li] = r1;
            out_loss[(2 * 3 + jj) * NN + li] = r2;
        }
    }
}

extern "C" void kernel_launch(void* const* d_in, const int* in_sizes, int n_in,
                              void* d_out, int out_size) {
    const int*   layout = (const int*)d_in[0];
    const float* flow   = (const float*)d_in[1];
    const size_t NP = (size_t)GNX * GNY;

    const int*   lay = layout + NP;        // layout[0,1]
    const float* f0  = flow;               // u channel
    const float* f1  = flow + NP;          // v channel
    const float* f2  = flow + 2 * NP;      // p channel

    float* out      = (float*)d_out;
    float* out_loss = out;
    float* out_mask = out_loss + (size_t)9 * (GNX - 2) * (GNY - 2);
    float* out_gbv  = out_mask + 3 * NP;

    row_flags_kernel<<<GNY, 256>>>(lay);

    dim3 block(TSX, TSY);
    dim3 grid(GNX / TSX, GNY / TSY);
    nse_main_kernel<<<grid, block>>>(lay, f0, f1, f2, out_loss, out_mask, out_gbv);
}

// round 2
// speedup vs baseline: 1.2350x; 1.2350x over previous
#include <cuda_runtime.h>

// NSE_layer: fused NSE residual + BC-mask outputs, 2048x2048 grid.
// Output flat concat: loss (3,3,2046,2046) | mask (1,3,2048,2048) | gbv (2,1,3,2048,2048)

#define GNX 2048
#define GNY 2048
#define NNX 2046

__device__ unsigned char g_row_in[GNY];
__device__ unsigned char g_row_out[GNY];

__global__ void row_flags_kernel(const int* __restrict__ lay) {
    int y = blockIdx.x;
    const int* row = lay + (size_t)y * GNX;
    int fin = 0, fout = 0;
    for (int x = threadIdx.x; x < GNX; x += blockDim.x) {
        int L = __ldg(row + x);
        fin  |= (L == 1);
        fout |= (L == 3);
    }
    fin  = __syncthreads_or(fin);
    fout = __syncthreads_or(fout);
    if (threadIdx.x == 0) {
        g_row_in[y]  = (unsigned char)(fin  ? 1 : 0);
        g_row_out[y] = (unsigned char)(fout ? 1 : 0);
    }
}

// ---------------- mask + gbv kernel: 4 pixels/thread, float4 I/O ----------------
__global__ __launch_bounds__(256)
void mask_kernel(const int* __restrict__ lay,
                 float* __restrict__ out_mask,
                 float* __restrict__ out_gbv)
{
    const size_t NP = (size_t)GNX * GNY;
    int k = blockIdx.x * 32 + threadIdx.x;      // 0..511 (x-chunk)
    int Y = blockIdx.y * 8  + threadIdx.y;      // 0..2047
    size_t idx = (size_t)Y * GNX + 4 * k;

    int4 L4 = __ldg((const int4*)(lay + idx));
    int Ls[4] = {L4.x, L4.y, L4.z, L4.w};
    unsigned char rin  = g_row_in[Y];
    unsigned char rout = g_row_out[Y];

    float gb0[4], gb1[4], gb2[4], gv0[4], mk0[4], mk1[4], mk2[4];
    #pragma unroll
    for (int j = 0; j < 4; j++) {
        int L = Ls[j];
        float base = (L == 2) ? 0.f : 1.f;
        float a0 = base, a1 = base, a2 = base, v0 = 0.f;
        int X = 4 * k + j;
        if (X == 0 && rin)        { a0 = 0.f; a1 = 0.f; v0 = 3.f; }
        if (X == GNX - 1 && rout) { a2 = 0.f; }
        float keep = (L > 3) ? 0.f : 1.f;
        float code = (L > 3) ? (float)L : 0.f;
        gb0[j] = a0; gb1[j] = a1; gb2[j] = a2; gv0[j] = v0;
        mk0[j] = a0 * keep + code;
        mk1[j] = a1 * keep + code;
        mk2[j] = a2 * keep + code;
    }

    *(float4*)(out_mask + 0 * NP + idx) = make_float4(mk0[0], mk0[1], mk0[2], mk0[3]);
    *(float4*)(out_mask + 1 * NP + idx) = make_float4(mk1[0], mk1[1], mk1[2], mk1[3]);
    *(float4*)(out_mask + 2 * NP + idx) = make_float4(mk2[0], mk2[1], mk2[2], mk2[3]);

    *(float4*)(out_gbv + 0 * NP + idx) = make_float4(gb0[0], gb0[1], gb0[2], gb0[3]);
    *(float4*)(out_gbv + 1 * NP + idx) = make_float4(gb1[0], gb1[1], gb1[2], gb1[3]);
    *(float4*)(out_gbv + 2 * NP + idx) = make_float4(gb2[0], gb2[1], gb2[2], gb2[3]);
    *(float4*)(out_gbv + 3 * NP + idx) = make_float4(gv0[0], gv0[1], gv0[2], gv0[3]);
    float4 z = make_float4(0.f, 0.f, 0.f, 0.f);
    *(float4*)(out_gbv + 4 * NP + idx) = z;
    *(float4*)(out_gbv + 5 * NP + idx) = z;
}

// ---------------- loss kernel: 4 pixels/thread, float2 stores ----------------
// Loads masked u,v,p for one row: positions 0..5 map to x = xv..xv+5.
__device__ __forceinline__ void load_uvp_row(
    const float* __restrict__ f0, const float* __restrict__ f1,
    const float* __restrict__ f2, const int* __restrict__ lay,
    int r, int xv, bool tail,
    float* u, float* v, float* p, int* lf_out)
{
    size_t off = (size_t)r * GNX + xv;
    float4 ua = __ldg((const float4*)(f0 + off));
    float4 va = __ldg((const float4*)(f1 + off));
    float4 pa = __ldg((const float4*)(f2 + off));
    int4   la = __ldg((const int4*)(lay + off));
    float u4 = 0.f, u5 = 0.f, v4 = 0.f, v5 = 0.f, p4 = 0.f, p5 = 0.f;
    int   l4 = 0, l5 = 0;
    if (!tail) {
        float4 ub = __ldg((const float4*)(f0 + off + 4));
        float4 vb = __ldg((const float4*)(f1 + off + 4));
        float4 pb = __ldg((const float4*)(f2 + off + 4));
        int4   lb = __ldg((const int4*)(lay + off + 4));
        u4 = ub.x; u5 = ub.y; v4 = vb.x; v5 = vb.y; p4 = pb.x; p5 = pb.y;
        l4 = lb.x; l5 = lb.y;
    }
    float uf[6] = {ua.x, ua.y, ua.z, ua.w, u4, u5};
    float vf[6] = {va.x, va.y, va.z, va.w, v4, v5};
    float pf[6] = {pa.x, pa.y, pa.z, pa.w, p4, p5};
    int   lf[6] = {la.x, la.y, la.z, la.w, l4, l5};
    #pragma unroll
    for (int i = 0; i < 6; i++) {
        float m = (lf[i] == 2) ? 0.f : 1.f;
        u[i] = uf[i] * m;
        v[i] = vf[i] * m;
        p[i] = pf[i] * m;
        if (lf_out) lf_out[i] = lf[i];
    }
    if (xv == 0 && g_row_in[r]) { u[0] = 3.f; v[0] = 0.f; }   // inlet col 0
    if (tail && g_row_out[r])   { p[3] = 0.f; }               // outlet col 2047 (pos 3)
}

__global__ __launch_bounds__(256)
void loss_kernel(const int* __restrict__ lay,
                 const float* __restrict__ f0,
                 const float* __restrict__ f1,
                 const float* __restrict__ f2,
                 float* __restrict__ out_loss)
{
    const size_t NN = (size_t)NNX * NNX;
    int k = blockIdx.x * 32 + threadIdx.x;        // 0..511
    int Y = blockIdx.y * 8  + threadIdx.y + 1;    // 1..2048 (predicated)
    if (Y > GNY - 2) return;
    bool tail = (k == 511);
    int  xv   = 4 * k;                            // aligned load base; pixels X = xv+1 .. xv+4

    float un[6], vn[6], pn[6];   // row Y-1
    float uc[6], vc[6], pc[6];   // row Y
    float us[6], vs[6], ps[6];   // row Y+1
    int   lc[6];
    load_uvp_row(f0, f1, f2, lay, Y - 1, xv, tail, un, vn, pn, (int*)0);
    load_uvp_row(f0, f1, f2, lay, Y,     xv, tail, uc, vc, pc, lc);
    load_uvp_row(f0, f1, f2, lay, Y + 1, xv, tail, us, vs, ps, (int*)0);

    const float h     = (float)(0.1 / 2047.0);
    const float inv_h = 1.0f / h;
    const float nu_h2 = 0.05f / (h * h);

    float r0[4], r1[4], r2[4];
    #pragma unroll
    for (int j = 0; j < 4; j++) {
        int   L   = lc[j + 1];
        float Uc  = uc[j + 1], Vc = vc[j + 1];
        float dxu = 0.5f * (uc[j + 2] - uc[j]);
        float dyu = 0.5f * (us[j + 1] - un[j + 1]);
        float dxv = 0.5f * (vc[j + 2] - vc[j]);
        float dyv = 0.5f * (vs[j + 1] - vn[j + 1]);
        float lapu = un[j + 1] + us[j + 1] + uc[j] + uc[j + 2] - 4.0f * Uc;
        float lapv = vn[j + 1] + vs[j + 1] + vc[j] + vc[j + 2] - 4.0f * Vc;
        float cont = dxu * inv_h + dyv * inv_h;

        bool fx  = (L == 4) | (L == 8)  | (L == 11);
        bool bx  = (L == 6) | (L == 9)  | (L == 10);
        bool fy  = (L == 7) | (L == 10) | (L == 11);
        bool by  = (L == 5) | (L == 8)  | (L == 9);
        float dpx = fx ? (pc[j + 2] - pc[j + 1]) : (bx ? (pc[j + 1] - pc[j]) : 0.5f * (pc[j + 2] - pc[j]));
        float dpy = fy ? (pn[j + 1] - pc[j + 1]) : (by ? (pc[j + 1] - ps[j + 1]) : 0.5f * (ps[j + 1] - pn[j + 1]));

        float mu = Uc * dxu * inv_h + Vc * dyu * inv_h + dpx * inv_h - lapu * nu_h2;
        float mv = Uc * dxv * inv_h + Vc * dyv * inv_h + dpy * inv_h - lapv * nu_h2;

        float m = (L == 2) ? 0.f : 1.f;
        r0[j] = m * mu; r1[j] = m * mv; r2[j] = m * cont;
    }

    size_t li = (size_t)(Y - 1) * NNX + 4 * k;    // even -> float2-aligned
    float2 a0 = make_float2(r0[0], r0[1]), b0 = make_float2(r0[2], r0[3]);
    float2 a1 = make_float2(r1[0], r1[1]), b1 = make_float2(r1[2], r1[3]);
    float2 a2 = make_float2(r2[0], r2[1]), b2 = make_float2(r2[2], r2[3]);
    #pragma unroll
    for (int rep = 0; rep < 3; rep++) {
        float* p0 = out_loss + (size_t)(0 * 3 + rep) * NN + li;
        float* p1 = out_loss + (size_t)(1 * 3 + rep) * NN + li;
        float* p2 = out_loss + (size_t)(2 * 3 + rep) * NN + li;
        *(float2*)p0 = a0;
        *(float2*)p1 = a1;
        *(float2*)p2 = a2;
        if (!tail) {
            *(float2*)(p0 + 2) = b0;
            *(float2*)(p1 + 2) = b1;
            *(float2*)(p2 + 2) = b2;
        }
    }
}

extern "C" void kernel_launch(void* const* d_in, const int* in_sizes, int n_in,
                              void* d_out, int out_size) {
    const int*   layout = (const int*)d_in[0];
    const float* flow   = (const float*)d_in[1];
    const size_t NP = (size_t)GNX * GNY;
    const size_t NN = (size_t)NNX * NNX;

    const int*   lay = layout + NP;        // layout[0,1]
    const float* f0  = flow;
    const float* f1  = flow + NP;
    const float* f2  = flow + 2 * NP;

    float* out      = (float*)d_out;
    float* out_loss = out;
    float* out_mask = out_loss + 9 * NN;
    float* out_gbv  = out_mask + 3 * NP;

    row_flags_kernel<<<GNY, 256>>>(lay);

    dim3 block(32, 8);
    mask_kernel<<<dim3(16, 256), block>>>(lay, out_mask, out_gbv);
    loss_kernel<<<dim3(16, 256), block>>>(lay, f0, f1, f2, out_loss);
}

// round 3
// speedup vs baseline: 1.2532x; 1.0148x over previous
#include <cuda_runtime.h>

// NSE_layer: fused NSE residual + BC-mask outputs, 2048x2048 grid.
// Output flat concat: loss (3,3,2046,2046) | mask (1,3,2048,2048) | gbv (2,1,3,2048,2048)

#define GNX 2048
#define GNY 2048
#define NNX 2046

__device__ unsigned char g_row_in[GNY];
__device__ unsigned char g_row_out[GNY];

// 4 rows per block, int4 loads, independent accumulators -> MLP-bound
__global__ __launch_bounds__(256)
void row_flags_kernel(const int* __restrict__ lay) {
    int y0 = blockIdx.x * 4;
    int fin[4], fout[4];
    #pragma unroll
    for (int r = 0; r < 4; r++) { fin[r] = 0; fout[r] = 0; }

    #pragma unroll
    for (int r = 0; r < 4; r++) {
        const int4* row = (const int4*)(lay + (size_t)(y0 + r) * GNX);
        #pragma unroll
        for (int i = 0; i < 2; i++) {
            int4 L = __ldg(row + threadIdx.x + i * 256);
            fin[r]  |= (L.x == 1) | (L.y == 1) | (L.z == 1) | (L.w == 1);
            fout[r] |= (L.x == 3) | (L.y == 3) | (L.z == 3) | (L.w == 3);
        }
    }
    #pragma unroll
    for (int r = 0; r < 4; r++) {
        int a = __syncthreads_or(fin[r]);
        int b = __syncthreads_or(fout[r]);
        if (threadIdx.x == 0) {
            g_row_in[y0 + r]  = (unsigned char)(a ? 1 : 0);
            g_row_out[y0 + r] = (unsigned char)(b ? 1 : 0);
        }
    }
}

// ---------------- mask + gbv kernel: 4 pixels/thread, float4 I/O, streaming stores ----------------
__global__ __launch_bounds__(256)
void mask_kernel(const int* __restrict__ lay,
                 float* __restrict__ out_mask,
                 float* __restrict__ out_gbv)
{
    const size_t NP = (size_t)GNX * GNY;
    int k = blockIdx.x * 32 + threadIdx.x;      // 0..511 (x-chunk)
    int Y = blockIdx.y * 8  + threadIdx.y;      // 0..2047
    size_t idx = (size_t)Y * GNX + 4 * k;

    int4 L4 = __ldg((const int4*)(lay + idx));
    int Ls[4] = {L4.x, L4.y, L4.z, L4.w};
    unsigned char rin  = g_row_in[Y];
    unsigned char rout = g_row_out[Y];

    float gb0[4], gb1[4], gb2[4], gv0[4], mk0[4], mk1[4], mk2[4];
    #pragma unroll
    for (int j = 0; j < 4; j++) {
        int L = Ls[j];
        float base = (L == 2) ? 0.f : 1.f;
        float a0 = base, a1 = base, a2 = base, v0 = 0.f;
        int X = 4 * k + j;
        if (X == 0 && rin)        { a0 = 0.f; a1 = 0.f; v0 = 3.f; }
        if (X == GNX - 1 && rout) { a2 = 0.f; }
        float keep = (L > 3) ? 0.f : 1.f;
        float code = (L > 3) ? (float)L : 0.f;
        gb0[j] = a0; gb1[j] = a1; gb2[j] = a2; gv0[j] = v0;
        mk0[j] = a0 * keep + code;
        mk1[j] = a1 * keep + code;
        mk2[j] = a2 * keep + code;
    }

    __stcs((float4*)(out_mask + 0 * NP + idx), make_float4(mk0[0], mk0[1], mk0[2], mk0[3]));
    __stcs((float4*)(out_mask + 1 * NP + idx), make_float4(mk1[0], mk1[1], mk1[2], mk1[3]));
    __stcs((float4*)(out_mask + 2 * NP + idx), make_float4(mk2[0], mk2[1], mk2[2], mk2[3]));

    __stcs((float4*)(out_gbv + 0 * NP + idx), make_float4(gb0[0], gb0[1], gb0[2], gb0[3]));
    __stcs((float4*)(out_gbv + 1 * NP + idx), make_float4(gb1[0], gb1[1], gb1[2], gb1[3]));
    __stcs((float4*)(out_gbv + 2 * NP + idx), make_float4(gb2[0], gb2[1], gb2[2], gb2[3]));
    __stcs((float4*)(out_gbv + 3 * NP + idx), make_float4(gv0[0], gv0[1], gv0[2], gv0[3]));
    float4 z = make_float4(0.f, 0.f, 0.f, 0.f);
    __stcs((float4*)(out_gbv + 4 * NP + idx), z);
    __stcs((float4*)(out_gbv + 5 * NP + idx), z);
}

// ---------------- loss kernel: 4 pixels/thread, float2 streaming stores ----------------
__device__ __forceinline__ void load_uvp_row(
    const float* __restrict__ f0, const float* __restrict__ f1,
    const float* __restrict__ f2, const int* __restrict__ lay,
    int r, int xv, bool tail,
    float* u, float* v, float* p, int* lf_out)
{
    size_t off = (size_t)r * GNX + xv;
    float4 ua = __ldg((const float4*)(f0 + off));
    float4 va = __ldg((const float4*)(f1 + off));
    float4 pa = __ldg((const float4*)(f2 + off));
    int4   la = __ldg((const int4*)(lay + off));
    float u4 = 0.f, u5 = 0.f, v4 = 0.f, v5 = 0.f, p4 = 0.f, p5 = 0.f;
    int   l4 = 0, l5 = 0;
    if (!tail) {
        float4 ub = __ldg((const float4*)(f0 + off + 4));
        float4 vb = __ldg((const float4*)(f1 + off + 4));
        float4 pb = __ldg((const float4*)(f2 + off + 4));
        int4   lb = __ldg((const int4*)(lay + off + 4));
        u4 = ub.x; u5 = ub.y; v4 = vb.x; v5 = vb.y; p4 = pb.x; p5 = pb.y;
        l4 = lb.x; l5 = lb.y;
    }
    float uf[6] = {ua.x, ua.y, ua.z, ua.w, u4, u5};
    float vf[6] = {va.x, va.y, va.z, va.w, v4, v5};
    float pf[6] = {pa.x, pa.y, pa.z, pa.w, p4, p5};
    int   lf[6] = {la.x, la.y, la.z, la.w, l4, l5};
    #pragma unroll
    for (int i = 0; i < 6; i++) {
        float m = (lf[i] == 2) ? 0.f : 1.f;
        u[i] = uf[i] * m;
        v[i] = vf[i] * m;
        p[i] = pf[i] * m;
        if (lf_out) lf_out[i] = lf[i];
    }
    if (xv == 0 && g_row_in[r]) { u[0] = 3.f; v[0] = 0.f; }   // inlet col 0
    if (tail && g_row_out[r])   { p[3] = 0.f; }               // outlet col 2047 (pos 3)
}

__global__ __launch_bounds__(256)
void loss_kernel(const int* __restrict__ lay,
                 const float* __restrict__ f0,
                 const float* __restrict__ f1,
                 const float* __restrict__ f2,
                 float* __restrict__ out_loss)
{
    const size_t NN = (size_t)NNX * NNX;
    int k = blockIdx.x * 32 + threadIdx.x;        // 0..511
    int Y = blockIdx.y * 8  + threadIdx.y + 1;    // 1..2048 (predicated)
    if (Y > GNY - 2) return;
    bool tail = (k == 511);
    int  xv   = 4 * k;                            // aligned load base; pixels X = xv+1 .. xv+4

    float un[6], vn[6], pn[6];   // row Y-1
    float uc[6], vc[6], pc[6];   // row Y
    float us[6], vs[6], ps[6];   // row Y+1
    int   lc[6];
    load_uvp_row(f0, f1, f2, lay, Y - 1, xv, tail, un, vn, pn, (int*)0);
    load_uvp_row(f0, f1, f2, lay, Y,     xv, tail, uc, vc, pc, lc);
    load_uvp_row(f0, f1, f2, lay, Y + 1, xv, tail, us, vs, ps, (int*)0);

    const float h     = (float)(0.1 / 2047.0);
    const float inv_h = 1.0f / h;
    const float nu_h2 = 0.05f / (h * h);

    float r0[4], r1[4], r2[4];
    #pragma unroll
    for (int j = 0; j < 4; j++) {
        int   L   = lc[j + 1];
        float Uc  = uc[j + 1], Vc = vc[j + 1];
        float dxu = 0.5f * (uc[j + 2] - uc[j]);
        float dyu = 0.5f * (us[j + 1] - un[j + 1]);
        float dxv = 0.5f * (vc[j + 2] - vc[j]);
        float dyv = 0.5f * (vs[j + 1] - vn[j + 1]);
        float lapu = un[j + 1] + us[j + 1] + uc[j] + uc[j + 2] - 4.0f * Uc;
        float lapv = vn[j + 1] + vs[j + 1] + vc[j] + vc[j + 2] - 4.0f * Vc;
        float cont = dxu * inv_h + dyv * inv_h;

        bool fx  = (L == 4) | (L == 8)  | (L == 11);
        bool bx  = (L == 6) | (L == 9)  | (L == 10);
        bool fy  = (L == 7) | (L == 10) | (L == 11);
        bool by  = (L == 5) | (L == 8)  | (L == 9);
        float dpx = fx ? (pc[j + 2] - pc[j + 1]) : (bx ? (pc[j + 1] - pc[j]) : 0.5f * (pc[j + 2] - pc[j]));
        float dpy = fy ? (pn[j + 1] - pc[j + 1]) : (by ? (pc[j + 1] - ps[j + 1]) : 0.5f * (ps[j + 1] - pn[j + 1]));

        float mu = Uc * dxu * inv_h + Vc * dyu * inv_h + dpx * inv_h - lapu * nu_h2;
        float mv = Uc * dxv * inv_h + Vc * dyv * inv_h + dpy * inv_h - lapv * nu_h2;

        float m = (L == 2) ? 0.f : 1.f;
        r0[j] = m * mu; r1[j] = m * mv; r2[j] = m * cont;
    }

    size_t li = (size_t)(Y - 1) * NNX + 4 * k;    // even -> float2-aligned
    float2 a0 = make_float2(r0[0], r0[1]), b0 = make_float2(r0[2], r0[3]);
    float2 a1 = make_float2(r1[0], r1[1]), b1 = make_float2(r1[2], r1[3]);
    float2 a2 = make_float2(r2[0], r2[1]), b2 = make_float2(r2[2], r2[3]);
    #pragma unroll
    for (int rep = 0; rep < 3; rep++) {
        float* p0 = out_loss + (size_t)(0 * 3 + rep) * NN + li;
        float* p1 = out_loss + (size_t)(1 * 3 + rep) * NN + li;
        float* p2 = out_loss + (size_t)(2 * 3 + rep) * NN + li;
        __stcs((float2*)p0, a0);
        __stcs((float2*)p1, a1);
        __stcs((float2*)p2, a2);
        if (!tail) {
            __stcs((float2*)(p0 + 2), b0);
            __stcs((float2*)(p1 + 2), b1);
            __stcs((float2*)(p2 + 2), b2);
        }
    }
}

extern "C" void kernel_launch(void* const* d_in, const int* in_sizes, int n_in,
                              void* d_out, int out_size) {
    const int*   layout = (const int*)d_in[0];
    const float* flow   = (const float*)d_in[1];
    const size_t NP = (size_t)GNX * GNY;
    const size_t NN = (size_t)NNX * NNX;

    const int*   lay = layout + NP;        // layout[0,1]
    const float* f0  = flow;
    const float* f1  = flow + NP;
    const float* f2  = flow + 2 * NP;

    float* out      = (float*)d_out;
    float* out_loss = out;
    float* out_mask = out_loss + 9 * NN;
    float* out_gbv  = out_mask + 3 * NP;

    row_flags_kernel<<<GNY / 4, 256>>>(lay);

    dim3 block(32, 8);
    mask_kernel<<<dim3(16, 256), block>>>(lay, out_mask, out_gbv);
    loss_kernel<<<dim3(16, 256), block>>>(lay, f0, f1, f2, out_loss);
}

// round 4
// speedup vs baseline: 1.3574x; 1.0831x over previous
#include <cuda_runtime.h>

// NSE_layer: fused NSE residual + BC-mask outputs, 2048x2048 grid.
// Output flat concat: loss (3,3,2046,2046) | mask (1,3,2048,2048) | gbv (2,1,3,2048,2048)

#define GNX 2048
#define GNY 2048
#define NNX 2046

__device__ unsigned char g_row_in[GNY];
__device__ unsigned char g_row_out[GNY];

// Warp-per-row flags: 16 independent LDG.128 per lane, warp-or reduction, no barriers.
__global__ __launch_bounds__(256)
void row_flags_kernel(const int* __restrict__ lay) {
    int warp = threadIdx.x >> 5;
    int lane = threadIdx.x & 31;
    int y = blockIdx.x * 8 + warp;
    const int4* row = (const int4*)(lay + (size_t)y * GNX);   // 512 int4 per row
    int f = 0;
    #pragma unroll
    for (int i = 0; i < 16; i++) {
        int4 L = __ldg(row + lane + 32 * i);
        f |= ((L.x == 1) | (L.y == 1) | (L.z == 1) | (L.w == 1));
        f |= ((L.x == 3) | (L.y == 3) | (L.z == 3) | (L.w == 3)) << 1;
    }
    f = __reduce_or_sync(0xffffffffu, f);
    if (lane == 0) {
        g_row_in[y]  = (unsigned char)(f & 1);
        g_row_out[y] = (unsigned char)((f >> 1) & 1);
    }
}

// ---------------- mask + gbv kernel: 4 pixels/thread, float4 I/O, streaming stores ----------------
__global__ __launch_bounds__(256)
void mask_kernel(const int* __restrict__ lay,
                 float* __restrict__ out_mask,
                 float* __restrict__ out_gbv)
{
    const size_t NP = (size_t)GNX * GNY;
    int k = blockIdx.x * 32 + threadIdx.x;      // 0..511 (x-chunk)
    int Y = blockIdx.y * 8  + threadIdx.y;      // 0..2047
    size_t idx = (size_t)Y * GNX + 4 * k;

    int4 L4 = __ldg((const int4*)(lay + idx));
    int Ls[4] = {L4.x, L4.y, L4.z, L4.w};
    unsigned char rin  = g_row_in[Y];
    unsigned char rout = g_row_out[Y];

    float gb0[4], gb1[4], gb2[4], gv0[4], mk0[4], mk1[4], mk2[4];
    #pragma unroll
    for (int j = 0; j < 4; j++) {
        int L = Ls[j];
        float base = (L == 2) ? 0.f : 1.f;
        float a0 = base, a1 = base, a2 = base, v0 = 0.f;
        int X = 4 * k + j;
        if (X == 0 && rin)        { a0 = 0.f; a1 = 0.f; v0 = 3.f; }
        if (X == GNX - 1 && rout) { a2 = 0.f; }
        float keep = (L > 3) ? 0.f : 1.f;
        float code = (L > 3) ? (float)L : 0.f;
        gb0[j] = a0; gb1[j] = a1; gb2[j] = a2; gv0[j] = v0;
        mk0[j] = a0 * keep + code;
        mk1[j] = a1 * keep + code;
        mk2[j] = a2 * keep + code;
    }

    __stcs((float4*)(out_mask + 0 * NP + idx), make_float4(mk0[0], mk0[1], mk0[2], mk0[3]));
    __stcs((float4*)(out_mask + 1 * NP + idx), make_float4(mk1[0], mk1[1], mk1[2], mk1[3]));
    __stcs((float4*)(out_mask + 2 * NP + idx), make_float4(mk2[0], mk2[1], mk2[2], mk2[3]));

    __stcs((float4*)(out_gbv + 0 * NP + idx), make_float4(gb0[0], gb0[1], gb0[2], gb0[3]));
    __stcs((float4*)(out_gbv + 1 * NP + idx), make_float4(gb1[0], gb1[1], gb1[2], gb1[3]));
    __stcs((float4*)(out_gbv + 2 * NP + idx), make_float4(gb2[0], gb2[1], gb2[2], gb2[3]));
    __stcs((float4*)(out_gbv + 3 * NP + idx), make_float4(gv0[0], gv0[1], gv0[2], gv0[3]));
    float4 z = make_float4(0.f, 0.f, 0.f, 0.f);
    __stcs((float4*)(out_gbv + 4 * NP + idx), z);
    __stcs((float4*)(out_gbv + 5 * NP + idx), z);
}

// ---------------- loss kernel: 4 pixels/thread, float2 streaming stores ----------------
__device__ __forceinline__ void load_uvp_row(
    const float* __restrict__ f0, const float* __restrict__ f1,
    const float* __restrict__ f2, const int* __restrict__ lay,
    int r, int xv, bool tail,
    float* u, float* v, float* p, int* lf_out)
{
    size_t off = (size_t)r * GNX + xv;
    float4 ua = __ldg((const float4*)(f0 + off));
    float4 va = __ldg((const float4*)(f1 + off));
    float4 pa = __ldg((const float4*)(f2 + off));
    int4   la = __ldg((const int4*)(lay + off));
    float u4 = 0.f, u5 = 0.f, v4 = 0.f, v5 = 0.f, p4 = 0.f, p5 = 0.f;
    int   l4 = 0, l5 = 0;
    if (!tail) {
        float4 ub = __ldg((const float4*)(f0 + off + 4));
        float4 vb = __ldg((const float4*)(f1 + off + 4));
        float4 pb = __ldg((const float4*)(f2 + off + 4));
        int4   lb = __ldg((const int4*)(lay + off + 4));
        u4 = ub.x; u5 = ub.y; v4 = vb.x; v5 = vb.y; p4 = pb.x; p5 = pb.y;
        l4 = lb.x; l5 = lb.y;
    }
    float uf[6] = {ua.x, ua.y, ua.z, ua.w, u4, u5};
    float vf[6] = {va.x, va.y, va.z, va.w, v4, v5};
    float pf[6] = {pa.x, pa.y, pa.z, pa.w, p4, p5};
    int   lf[6] = {la.x, la.y, la.z, la.w, l4, l5};
    #pragma unroll
    for (int i = 0; i < 6; i++) {
        float m = (lf[i] == 2) ? 0.f : 1.f;
        u[i] = uf[i] * m;
        v[i] = vf[i] * m;
        p[i] = pf[i] * m;
        if (lf_out) lf_out[i] = lf[i];
    }
    if (xv == 0 && g_row_in[r]) { u[0] = 3.f; v[0] = 0.f; }   // inlet col 0
    if (tail && g_row_out[r])   { p[3] = 0.f; }               // outlet col 2047 (pos 3)
}

__global__ __launch_bounds__(256)
void loss_kernel(const int* __restrict__ lay,
                 const float* __restrict__ f0,
                 const float* __restrict__ f1,
                 const float* __restrict__ f2,
                 float* __restrict__ out_loss)
{
    const size_t NN = (size_t)NNX * NNX;
    int k = blockIdx.x * 32 + threadIdx.x;        // 0..511
    int Y = blockIdx.y * 8  + threadIdx.y + 1;    // 1..2048 (predicated)
    if (Y > GNY - 2) return;
    bool tail = (k == 511);
    int  xv   = 4 * k;                            // aligned load base; pixels X = xv+1 .. xv+4

    float un[6], vn[6], pn[6];   // row Y-1
    float uc[6], vc[6], pc[6];   // row Y
    float us[6], vs[6], ps[6];   // row Y+1
    int   lc[6];
    load_uvp_row(f0, f1, f2, lay, Y - 1, xv, tail, un, vn, pn, (int*)0);
    load_uvp_row(f0, f1, f2, lay, Y,     xv, tail, uc, vc, pc, lc);
    load_uvp_row(f0, f1, f2, lay, Y + 1, xv, tail, us, vs, ps, (int*)0);

    const float h     = (float)(0.1 / 2047.0);
    const float inv_h = 1.0f / h;
    const float nu_h2 = 0.05f / (h * h);

    float r0[4], r1[4], r2[4];
    #pragma unroll
    for (int j = 0; j < 4; j++) {
        int   L   = lc[j + 1];
        float Uc  = uc[j + 1], Vc = vc[j + 1];
        float dxu = 0.5f * (uc[j + 2] - uc[j]);
        float dyu = 0.5f * (us[j + 1] - un[j + 1]);
        float dxv = 0.5f * (vc[j + 2] - vc[j]);
        float dyv = 0.5f * (vs[j + 1] - vn[j + 1]);
        float lapu = un[j + 1] + us[j + 1] + uc[j] + uc[j + 2] - 4.0f * Uc;
        float lapv = vn[j + 1] + vs[j + 1] + vc[j] + vc[j + 2] - 4.0f * Vc;
        float cont = dxu * inv_h + dyv * inv_h;

        bool fx  = (L == 4) | (L == 8)  | (L == 11);
        bool bx  = (L == 6) | (L == 9)  | (L == 10);
        bool fy  = (L == 7) | (L == 10) | (L == 11);
        bool by  = (L == 5) | (L == 8)  | (L == 9);
        float dpx = fx ? (pc[j + 2] - pc[j + 1]) : (bx ? (pc[j + 1] - pc[j]) : 0.5f * (pc[j + 2] - pc[j]));
        float dpy = fy ? (pn[j + 1] - pc[j + 1]) : (by ? (pc[j + 1] - ps[j + 1]) : 0.5f * (ps[j + 1] - pn[j + 1]));

        float mu = Uc * dxu * inv_h + Vc * dyu * inv_h + dpx * inv_h - lapu * nu_h2;
        float mv = Uc * dxv * inv_h + Vc * dyv * inv_h + dpy * inv_h - lapv * nu_h2;

        float m = (L == 2) ? 0.f : 1.f;
        r0[j] = m * mu; r1[j] = m * mv; r2[j] = m * cont;
    }

    size_t li = (size_t)(Y - 1) * NNX + 4 * k;    // even -> float2-aligned
    float2 a0 = make_float2(r0[0], r0[1]), b0 = make_float2(r0[2], r0[3]);
    float2 a1 = make_float2(r1[0], r1[1]), b1 = make_float2(r1[2], r1[3]);
    float2 a2 = make_float2(r2[0], r2[1]), b2 = make_float2(r2[2], r2[3]);
    #pragma unroll
    for (int rep = 0; rep < 3; rep++) {
        float* p0 = out_loss + (size_t)(0 * 3 + rep) * NN + li;
        float* p1 = out_loss + (size_t)(1 * 3 + rep) * NN + li;
        float* p2 = out_loss + (size_t)(2 * 3 + rep) * NN + li;
        __stcs((float2*)p0, a0);
        __stcs((float2*)p1, a1);
        __stcs((float2*)p2, a2);
        if (!tail) {
            __stcs((float2*)(p0 + 2), b0);
            __stcs((float2*)(p1 + 2), b1);
            __stcs((float2*)(p2 + 2), b2);
        }
    }
}

extern "C" void kernel_launch(void* const* d_in, const int* in_sizes, int n_in,
                              void* d_out, int out_size) {
    const int*   layout = (const int*)d_in[0];
    const float* flow   = (const float*)d_in[1];
    const size_t NP = (size_t)GNX * GNY;
    const size_t NN = (size_t)NNX * NNX;

    const int*   lay = layout + NP;        // layout[0,1]
    const float* f0  = flow;
    const float* f1  = flow + NP;
    const float* f2  = flow + 2 * NP;

    float* out      = (float*)d_out;
    float* out_loss = out;
    float* out_mask = out_loss + 9 * NN;
    float* out_gbv  = out_mask + 3 * NP;

    // One-time host-side stream/event setup (created on the first, uncaptured,
    // correctness call; reused identically on every call -> same captured graph).
    static cudaStream_t s_side = 0;
    static cudaEvent_t  ev_fork = 0, ev_join = 0;
    if (s_side == 0) {
        cudaStreamCreateWithFlags(&s_side, cudaStreamNonBlocking);
        cudaEventCreateWithFlags(&ev_fork, cudaEventDisableTiming);
        cudaEventCreateWithFlags(&ev_join, cudaEventDisableTiming);
    }

    row_flags_kernel<<<GNY / 8, 256>>>(lay);

    // Fork: mask on side stream, loss on main stream, both after flags.
    cudaEventRecord(ev_fork, 0);
    cudaStreamWaitEvent(s_side, ev_fork, 0);

    dim3 block(32, 8);
    mask_kernel<<<dim3(16, 256), block, 0, s_side>>>(lay, out_mask, out_gbv);
    loss_kernel<<<dim3(16, 256), block>>>(lay, f0, f1, f2, out_loss);

    // Join back onto the main (captured) stream.
    cudaEventRecord(ev_join, s_side);
    cudaStreamWaitEvent(0, ev_join, 0);
}